// round 11
// baseline (speedup 1.0000x reference)
#include <cuda_runtime.h>
#include <cuda_fp16.h>
#include <cstdint>

#define Hh 512
#define Ww 512
#define CIN 64
#define KOC 128
#define HWSZ (Hh*Ww)
#define NT 9

#define SWZ(o) ((o) ^ ((((uint32_t)(o))>>3)&0x70))

// ---- dynamic smem layout (57.75 KB -> 3 CTAs/SM) ----
#define SCL    0
#define SHF    512
#define ABASE  1024
#define AROWS  66
#define ABUFSZ (AROWS*128)                   // 8448
#define ABUF(dy) (ABASE + (dy)*ABUFSZ)       // 3 buffers (dy 0..2), fp16
#define WBASE  (ABASE + 3*ABUFSZ)            // 26368
#define WBUF(b) (WBASE + (b)*16384)          // double-buffered W, fp16
#define SMEM_TOTAL (WBASE + 2*16384)         // 59136

__device__ __align__(16) unsigned char Wb[NT*16384];   // pre-swizzled fp16 W tiles

static __device__ __forceinline__ uint32_t s2u(const void* p){
    uint32_t a;
    asm("{ .reg .u64 t; cvta.to.shared.u64 t, %1; cvt.u32.u64 %0, t; }":"=r"(a):"l"(p));
    return a;
}
static __device__ __forceinline__ void ldsm4(uint32_t addr,
        uint32_t &r0, uint32_t &r1, uint32_t &r2, uint32_t &r3){
    asm volatile("ldmatrix.sync.aligned.m8n8.x4.shared.b16 {%0,%1,%2,%3}, [%4];"
        : "=r"(r0),"=r"(r1),"=r"(r2),"=r"(r3) : "r"(addr));
}
static __device__ __forceinline__ void hmma(float* c,
        uint32_t a0,uint32_t a1,uint32_t a2,uint32_t a3,
        uint32_t b0,uint32_t b1){
    asm volatile("mma.sync.aligned.m16n8k16.row.col.f32.f16.f16.f32 "
        "{%0,%1,%2,%3}, {%4,%5,%6,%7}, {%8,%9}, {%0,%1,%2,%3};"
        : "+f"(c[0]),"+f"(c[1]),"+f"(c[2]),"+f"(c[3])
        : "r"(a0),"r"(a1),"r"(a2),"r"(a3),"r"(b0),"r"(b1));
}
static __device__ __forceinline__ void cpasync16(uint32_t daddr, const void* g){
    asm volatile("cp.async.cg.shared.global [%0], [%1], 16;" :: "r"(daddr), "l"(g) : "memory");
}
static __device__ __forceinline__ void cpcommit(){
    asm volatile("cp.async.commit_group;" ::: "memory");
}
template<int N> static __device__ __forceinline__ void cpwait(){
    asm volatile("cp.async.wait_group %0;" :: "n"(N) : "memory");
}

// ---------- prep: W -> fp16, pre-swizzled K-major SW128 tiles ----------
__global__ void prep_w(const float* __restrict__ Wt){
    int idx = blockIdx.x * blockDim.x + threadIdx.x;   // 9*128*64
    if (idx >= NT*KOC*CIN) return;
    int t   = idx >> 13;
    int rem = idx & 8191;
    int n   = rem >> 6;
    int kk  = rem & 63;
    float v = Wt[(n*CIN + kk)*9 + t];
    uint32_t off = SWZ((uint32_t)(n*128 + kk*2));
    *(__half*)(Wb + t*16384 + off) = __float2half_rn(v);
}

// ---------- main fused kernel: fp16 1-pass, CTA M=64 x N=128, 3 CTAs/SM ----------
__global__ void __launch_bounds__(256,3)
conv_mma_f16(const float* __restrict__ x,
             const float* __restrict__ gamma, const float* __restrict__ beta,
             const float* __restrict__ mean,  const float* __restrict__ var,
             const int*   __restrict__ mask,  float* __restrict__ out)
{
    extern __shared__ __align__(1024) char sm[];
    const uint32_t smb = s2u(sm);

    const int tid  = threadIdx.x;
    const int w    = tid >> 5;
    const int lane = tid & 31;
    const int wm   = w >> 2;           // 0..1 : m offset wm*32
    const int wn   = w & 3;            // 0..3 : n offset wn*32

    float* s_scale = (float*)(sm + SCL);
    float* s_shift = (float*)(sm + SHF);
    if (tid < KOC) {
        float sc = gamma[tid] * rsqrtf(var[tid] + 1e-5f);
        s_scale[tid] = sc;
        s_shift[tid] = beta[tid] - mean[tid] * sc;
    }

    const int bid  = blockIdx.x;       // 4096
    const int r    = bid >> 3;         // image row
    const int col0 = (bid & 7) * 64;   // 64-col tile

    float acc[2][4][4];
    #pragma unroll
    for (int m = 0; m < 2; ++m)
        #pragma unroll
        for (int n = 0; n < 4; ++n)
            #pragma unroll
            for (int e = 0; e < 4; ++e) acc[m][n][e] = 0.f;

    // ldmatrix lane geometry
    const int jj = lane >> 3, rr = lane & 7;
    const int a_row_l = ((jj & 1) << 3) + rr;
    const int a_col_l = (jj >> 1) << 4;
    const int b_row_l = ((jj >> 1) << 3) + rr;
    const int b_col_l = (jj & 1) << 4;

    // ---- prologue: async-prefetch W tap 0 ----
    {
        const uint32_t d = smb + WBUF(0);
        #pragma unroll
        for (int p = 0; p < 4; ++p)
            cpasync16(d + (tid + p*256)*16, (const char*)Wb + (tid + p*256)*16);
        cpcommit();
    }

    // ---- persistent A (fp16): buffer row i <-> image column col0-1+i, i in [0,66) ----
    #pragma unroll
    for (int dy = 0; dy < 3; ++dy) {
        int srow = r + dy - 1;
        srow = (srow < 0) ? -srow : ((srow > Hh-1) ? (2*Hh-2 - srow) : srow);
        const float* xrow = x + (size_t)srow * Ww;
        #pragma unroll
        for (int ii = 0; ii < 3; ++ii) {
            const int ipix = lane + 32*ii;
            if (ipix < AROWS) {
                int cc = col0 - 1 + ipix;
                cc = (cc < 0) ? -cc : ((cc > Ww-1) ? (2*Ww-2 - cc) : cc);
                float v[8];
                #pragma unroll
                for (int j = 0; j < 8; ++j)
                    v[j] = __ldg(xrow + (size_t)(w*8 + j) * HWSZ + cc);
                uint32_t hw4[4];
                #pragma unroll
                for (int q = 0; q < 4; ++q) {
                    __half2 hp = __floats2half2_rn(v[2*q], v[2*q+1]);
                    hw4[q] = *(uint32_t*)&hp;
                }
                const uint32_t off = SWZ((uint32_t)(ipix*128 + w*16));
                *(uint4*)(sm + ABUF(dy) + off) = make_uint4(hw4[0],hw4[1],hw4[2],hw4[3]);
            }
        }
    }

    // ---- main loop over 9 taps, W double-buffered via cp.async ----
    for (int ch = 0; ch < NT; ++ch) {
        __syncthreads();     // all reads of WBUF((ch+1)&1) from tap ch-1 complete

        if (ch + 1 < NT) {   // prefetch W(ch+1) into the other buffer
            const uint32_t d = smb + WBUF((ch+1) & 1);
            const char* sh = (const char*)Wb + (ch+1)*16384;
            #pragma unroll
            for (int p = 0; p < 4; ++p)
                cpasync16(d + (tid + p*256)*16, sh + (tid + p*256)*16);
            cpcommit();
            cpwait<1>();     // W(ch) has landed
        } else {
            cpwait<0>();
        }
        __syncthreads();     // W(ch) (+ A staging at ch=0) visible to all warps

        const int dyi    = ch / 3;
        const int rowoff = (ch % 3);         // dx+1
        const uint32_t wb = smb + WBUF(ch & 1);
        const uint32_t ab = smb + ABUF(dyi);

        #pragma unroll
        for (int ks = 0; ks < 4; ++ks) {
            const int kbyte = ks*32;
            uint32_t bh[8];
            #pragma unroll
            for (int np = 0; np < 2; ++np) {
                const int brow = wn*32 + np*16 + b_row_l;
                const uint32_t boff = SWZ((uint32_t)(brow*128 + kbyte + b_col_l));
                ldsm4(wb + boff, bh[np*4+0], bh[np*4+1], bh[np*4+2], bh[np*4+3]);
            }
            #pragma unroll
            for (int msub = 0; msub < 2; ++msub) {
                const int arow = wm*32 + msub*16 + a_row_l + rowoff;
                const uint32_t aoff = SWZ((uint32_t)(arow*128 + kbyte + a_col_l));
                uint32_t ah[4];
                ldsm4(ab + aoff, ah[0], ah[1], ah[2], ah[3]);
                #pragma unroll
                for (int nsub = 0; nsub < 4; ++nsub)
                    hmma(acc[msub][nsub], ah[0],ah[1],ah[2],ah[3],
                         bh[nsub*2], bh[nsub*2+1]);
            }
        }
    }

    // ---------------- epilogue: BN + LeakyReLU + mask ----------------
    const int mrow = lane >> 2;
    const int ncol = (lane & 3) << 1;
    #pragma unroll
    for (int msub = 0; msub < 2; ++msub) {
        const int pix0 = r*Ww + col0 + wm*32 + msub*16 + mrow;
        #pragma unroll
        for (int nsub = 0; nsub < 4; ++nsub) {
            const int oc0 = wn*32 + nsub*8 + ncol;
            #pragma unroll
            for (int h = 0; h < 2; ++h) {
                const int pix = pix0 + h*8;
                #pragma unroll
                for (int e = 0; e < 2; ++e) {
                    const int oc = oc0 + e;
                    float y = fmaf(acc[msub][nsub][h*2+e], s_scale[oc], s_shift[oc]);
                    y = (y >= 0.f) ? y : 0.01f * y;
                    const int base = oc*HWSZ + pix;
                    out[base] = y * (float)mask[base];
                }
            }
        }
    }
}

extern "C" void kernel_launch(void* const* d_in, const int* in_sizes, int n_in,
                              void* d_out, int out_size)
{
    const float* x     = (const float*)d_in[0];
    const float* Wt    = (const float*)d_in[1];
    const float* gamma = (const float*)d_in[2];
    const float* beta  = (const float*)d_in[3];
    const float* mean  = (const float*)d_in[4];
    const float* var   = (const float*)d_in[5];
    const int*   mask  = (const int*)d_in[6];
    float*       out   = (float*)d_out;

    cudaFuncSetAttribute(conv_mma_f16, cudaFuncAttributeMaxDynamicSharedMemorySize, SMEM_TOTAL);

    prep_w<<<(NT*KOC*CIN + 255)/256, 256>>>(Wt);
    conv_mma_f16<<<4096, 256, SMEM_TOTAL>>>(x, gamma, beta, mean, var, mask, out);
}

// round 12
// speedup vs baseline: 1.1390x; 1.1390x over previous
#include <cuda_runtime.h>
#include <cuda_fp16.h>
#include <cstdint>

#define Hh 512
#define Ww 512
#define CIN 64
#define KOC 128
#define HWSZ (Hh*Ww)
#define NT 9

#define SWZ(o) ((o) ^ ((((uint32_t)(o))>>3)&0x70))

// ---- dynamic smem layout (84 KB -> 2 CTAs/SM) ----
#define SCL    0
#define SHF    512
#define ABASE  1024
#define AROWS  136
#define ABUFSZ (AROWS*128)                   // 17408
#define ABUF(dy) (ABASE + (dy)*ABUFSZ)       // 3 buffers (dy 0..2), fp16 pixels
#define WBASE  (ABASE + 3*ABUFSZ)            // 53248
#define WBUF(b) (WBASE + (b)*16384)          // double-buffered W, fp16
#define SMEM_TOTAL (WBASE + 2*16384)         // 86016

__device__ __align__(16) unsigned char Wb[NT*16384];   // pre-swizzled fp16 W tiles

static __device__ __forceinline__ uint32_t s2u(const void* p){
    uint32_t a;
    asm("{ .reg .u64 t; cvta.to.shared.u64 t, %1; cvt.u32.u64 %0, t; }":"=r"(a):"l"(p));
    return a;
}
static __device__ __forceinline__ void ldsm4(uint32_t addr,
        uint32_t &r0, uint32_t &r1, uint32_t &r2, uint32_t &r3){
    asm volatile("ldmatrix.sync.aligned.m8n8.x4.shared.b16 {%0,%1,%2,%3}, [%4];"
        : "=r"(r0),"=r"(r1),"=r"(r2),"=r"(r3) : "r"(addr));
}
static __device__ __forceinline__ void hmma(float* c,
        uint32_t a0,uint32_t a1,uint32_t a2,uint32_t a3,
        uint32_t b0,uint32_t b1){
    asm volatile("mma.sync.aligned.m16n8k16.row.col.f32.f16.f16.f32 "
        "{%0,%1,%2,%3}, {%4,%5,%6,%7}, {%8,%9}, {%0,%1,%2,%3};"
        : "+f"(c[0]),"+f"(c[1]),"+f"(c[2]),"+f"(c[3])
        : "r"(a0),"r"(a1),"r"(a2),"r"(a3),"r"(b0),"r"(b1));
}
static __device__ __forceinline__ void cpasync16(uint32_t daddr, const void* g){
    asm volatile("cp.async.cg.shared.global [%0], [%1], 16;" :: "r"(daddr), "l"(g) : "memory");
}
static __device__ __forceinline__ void cpcommit(){
    asm volatile("cp.async.commit_group;" ::: "memory");
}
template<int N> static __device__ __forceinline__ void cpwait(){
    asm volatile("cp.async.wait_group %0;" :: "n"(N) : "memory");
}

// ---------- prep: W -> fp16, pre-swizzled K-major SW128 tiles (rows = oc) ----------
__global__ void prep_w(const float* __restrict__ Wt){
    int idx = blockIdx.x * blockDim.x + threadIdx.x;   // 9*128*64
    if (idx >= NT*KOC*CIN) return;
    int t   = idx >> 13;
    int rem = idx & 8191;
    int n   = rem >> 6;
    int kk  = rem & 63;
    float v = Wt[(n*CIN + kk)*9 + t];
    uint32_t off = SWZ((uint32_t)(n*128 + kk*2));
    *(__half*)(Wb + t*16384 + off) = __float2half_rn(v);
}

// ---------- main fused kernel: fp16 1-pass, M=oc(128) x N=pix(128), 2 CTAs/SM ----------
__global__ void __launch_bounds__(256,2)
conv_mma_f16(const float* __restrict__ x,
             const float* __restrict__ gamma, const float* __restrict__ beta,
             const float* __restrict__ mean,  const float* __restrict__ var,
             const int*   __restrict__ mask,  float* __restrict__ out)
{
    extern __shared__ __align__(1024) char sm[];
    const uint32_t smb = s2u(sm);

    const int tid  = threadIdx.x;
    const int w    = tid >> 5;
    const int lane = tid & 31;
    const int wpix = w >> 2;           // 0..1 : pixel offset wpix*64 (N dim)
    const int woc  = w & 3;            // 0..3 : oc offset woc*32   (M dim)

    float* s_scale = (float*)(sm + SCL);
    float* s_shift = (float*)(sm + SHF);
    if (tid < KOC) {
        float sc = gamma[tid] * rsqrtf(var[tid] + 1e-5f);
        s_scale[tid] = sc;
        s_shift[tid] = beta[tid] - mean[tid] * sc;
    }

    const int bid  = blockIdx.x;       // 2048
    const int r    = bid >> 2;         // image row
    const int col0 = (bid & 3) * 128;  // 128-col pixel tile

    // acc[msub(oc 16-blk)][n(pix 8-blk)][e] : D[oc][pix]
    float acc[2][8][4];
    #pragma unroll
    for (int m = 0; m < 2; ++m)
        #pragma unroll
        for (int n = 0; n < 8; ++n)
            #pragma unroll
            for (int e = 0; e < 4; ++e) acc[m][n][e] = 0.f;

    // ldmatrix lane geometry
    const int jj = lane >> 3, rr = lane & 7;
    const int a_row_l = ((jj & 1) << 3) + rr;
    const int a_col_l = (jj >> 1) << 4;
    const int b_row_l = ((jj >> 1) << 3) + rr;
    const int b_col_l = (jj & 1) << 4;

    // ---- prologue: async-prefetch W tap 0 ----
    {
        const uint32_t d = smb + WBUF(0);
        #pragma unroll
        for (int p = 0; p < 4; ++p)
            cpasync16(d + (tid + p*256)*16, (const char*)Wb + (tid + p*256)*16);
        cpcommit();
    }

    // ---- persistent pixel tiles (fp16): buffer row i <-> image col col0-1+i, i in [0,130) ----
    #pragma unroll
    for (int dy = 0; dy < 3; ++dy) {
        int srow = r + dy - 1;
        srow = (srow < 0) ? -srow : ((srow > Hh-1) ? (2*Hh-2 - srow) : srow);
        const float* xrow = x + (size_t)srow * Ww;
        #pragma unroll
        for (int ii = 0; ii < 5; ++ii) {
            const int ipix = lane + 32*ii;
            if (ipix < 130) {
                int cc = col0 - 1 + ipix;
                cc = (cc < 0) ? -cc : ((cc > Ww-1) ? (2*Ww-2 - cc) : cc);
                float v[8];
                #pragma unroll
                for (int j = 0; j < 8; ++j)
                    v[j] = __ldg(xrow + (size_t)(w*8 + j) * HWSZ + cc);
                uint32_t hw4[4];
                #pragma unroll
                for (int q = 0; q < 4; ++q) {
                    __half2 hp = __floats2half2_rn(v[2*q], v[2*q+1]);
                    hw4[q] = *(uint32_t*)&hp;
                }
                const uint32_t off = SWZ((uint32_t)(ipix*128 + w*16));
                *(uint4*)(sm + ABUF(dy) + off) = make_uint4(hw4[0],hw4[1],hw4[2],hw4[3]);
            }
        }
    }

    // ---- main loop over 9 taps, W double-buffered via cp.async ----
    for (int ch = 0; ch < NT; ++ch) {
        __syncthreads();     // all reads of WBUF((ch+1)&1) from tap ch-1 complete

        if (ch + 1 < NT) {   // prefetch W(ch+1) into the other buffer
            const uint32_t d = smb + WBUF((ch+1) & 1);
            const char* sh = (const char*)Wb + (ch+1)*16384;
            #pragma unroll
            for (int p = 0; p < 4; ++p)
                cpasync16(d + (tid + p*256)*16, sh + (tid + p*256)*16);
            cpcommit();
            cpwait<1>();     // W(ch) has landed
        } else {
            cpwait<0>();
        }
        __syncthreads();     // W(ch) (+ pixel staging at ch=0) visible to all warps

        const int dyi    = ch / 3;
        const int rowoff = (ch % 3);         // dx+1, applies to pixel rows (B side)
        const uint32_t wb = smb + WBUF(ch & 1);
        const uint32_t ab = smb + ABUF(dyi);

        #pragma unroll
        for (int ks = 0; ks < 4; ++ks) {
            const int kbyte = ks*32;
            uint32_t bp[16];                 // pixel B-frags: 64 pix = 4 ldsm4
            #pragma unroll
            for (int np = 0; np < 4; ++np) {
                const int prow = wpix*64 + np*16 + b_row_l + rowoff;
                const uint32_t poff = SWZ((uint32_t)(prow*128 + kbyte + b_col_l));
                ldsm4(ab + poff, bp[np*4+0], bp[np*4+1], bp[np*4+2], bp[np*4+3]);
            }
            #pragma unroll
            for (int msub = 0; msub < 2; ++msub) {
                const int wrow = woc*32 + msub*16 + a_row_l;
                const uint32_t woff = SWZ((uint32_t)(wrow*128 + kbyte + a_col_l));
                uint32_t ah[4];
                ldsm4(wb + woff, ah[0], ah[1], ah[2], ah[3]);
                #pragma unroll
                for (int n = 0; n < 8; ++n)
                    hmma(acc[msub][n], ah[0],ah[1],ah[2],ah[3],
                         bp[n*2], bp[n*2+1]);
            }
        }
    }

    // ---- epilogue: BN + LeakyReLU + mask, 2 consecutive pixels per lane (64b IO) ----
    const int pixc = (lane & 3) << 1;
    const int ocr  = lane >> 2;
    #pragma unroll
    for (int msub = 0; msub < 2; ++msub) {
        #pragma unroll
        for (int n = 0; n < 8; ++n) {
            const int pix = r*Ww + col0 + wpix*64 + n*8 + pixc;
            #pragma unroll
            for (int h = 0; h < 2; ++h) {
                const int oc = woc*32 + msub*16 + ocr + h*8;
                const float sc = s_scale[oc];
                const float sh = s_shift[oc];
                const int base = oc*HWSZ + pix;
                const int2 m2 = *(const int2*)(mask + base);
                float y0 = fmaf(acc[msub][n][h*2+0], sc, sh);
                float y1 = fmaf(acc[msub][n][h*2+1], sc, sh);
                y0 = (y0 >= 0.f) ? y0 : 0.01f * y0;
                y1 = (y1 >= 0.f) ? y1 : 0.01f * y1;
                float2 rv;
                rv.x = y0 * (float)m2.x;
                rv.y = y1 * (float)m2.y;
                *(float2*)(out + base) = rv;
            }
        }
    }
}

extern "C" void kernel_launch(void* const* d_in, const int* in_sizes, int n_in,
                              void* d_out, int out_size)
{
    const float* x     = (const float*)d_in[0];
    const float* Wt    = (const float*)d_in[1];
    const float* gamma = (const float*)d_in[2];
    const float* beta  = (const float*)d_in[3];
    const float* mean  = (const float*)d_in[4];
    const float* var   = (const float*)d_in[5];
    const int*   mask  = (const int*)d_in[6];
    float*       out   = (float*)d_out;

    cudaFuncSetAttribute(conv_mma_f16, cudaFuncAttributeMaxDynamicSharedMemorySize, SMEM_TOTAL);

    prep_w<<<(NT*KOC*CIN + 255)/256, 256>>>(Wt);
    conv_mma_f16<<<2048, 256, SMEM_TOTAL>>>(x, gamma, beta, mean, var, mask, out);
}